// round 17
// baseline (speedup 1.0000x reference)
#include <cuda_runtime.h>
#include <cuda_bf16.h>
#include <cuda_fp16.h>
#include <cstdint>
#include <math.h>

#define NN 4096
#define EE 131072
#define HH 256

#define QSCALE_F (0.17677669529663687f * 1.4426950408889634f)

// ---------------- scratch (static device globals; no allocation) ----------------
__device__ __half g_tmpH[NN*HH];     // h @ W, fp16 (pre-aggregation)
__device__ __half g_hH  [NN*HH];     // activation (fp16 GEMM input)
__device__ __half g_h3H [NN*HH];     // h3 fp16 (QKV GEMM input)
__device__ float  g_h3  [NN*HH];     // h3 fp32 (residual SRC)
__device__ __half g_attnH[NN*HH];    // attention output fp16
__device__ float g_po [2][NN*HH];    // split-KV partial O (unnormalized, fp32)
__device__ float g_pm [2*8*NN];      // split-KV partial max (log2 domain)
__device__ float g_pl [2*8*NN];      // split-KV partial sum
__device__ float g_deg [NN];
__device__ float g_dinv[NN];
__device__ float g_hid [NN*128];
__device__ float g_hid2[NN*128];
__device__ int   g_rowptr[NN+1];
__device__ int   g_cursor[NN];
__device__ int   g_esrc [EE];
__device__ float g_enorm[EE];
__device__ __nv_bfloat16 g_Qb[8*NN*32];   // [h][n][d], pre-scaled by 1/sqrt(32)*log2e
__device__ __nv_bfloat16 g_Kb[8*NN*32];   // [h][n][d]
__device__ __half        g_Vh[8*32*NN];   // [h][d][n]  (transposed, fp16)
// fp16 operand copies (built once per launch, overlapped)
__device__ __half g_xH  [NN*128];
__device__ __half g_W1t [256*128];        // [N,K]
__device__ __half g_W2t [256*256];
__device__ __half g_W3t [256*256];
__device__ __half g_inwH[768*256];
__device__ __half g_outwH[256*256];
__device__ __half g_fp1H[128*256];
__device__ __half g_pd1H[128*256];

// ---------------- async-copy helpers ---------------------------------------------
__device__ __forceinline__ void cp_async16(void* smem, const void* gmem) {
    uint32_t s = (uint32_t)__cvta_generic_to_shared(smem);
    asm volatile("cp.async.ca.shared.global [%0], [%1], 16;\n" :: "r"(s), "l"(gmem));
}
#define CP_COMMIT() asm volatile("cp.async.commit_group;\n" ::: "memory")
#define CP_WAIT(n)  asm volatile("cp.async.wait_group %0;\n" :: "n"(n) : "memory")

// ---------------- mma wrappers ----------------------------------------------------
__device__ __forceinline__ void mma_bf16(float* c, const uint32_t* a, uint32_t b0, uint32_t b1) {
    asm volatile(
        "mma.sync.aligned.m16n8k16.row.col.f32.bf16.bf16.f32 "
        "{%0,%1,%2,%3}, {%4,%5,%6,%7}, {%8,%9}, {%0,%1,%2,%3};\n"
        : "+f"(c[0]), "+f"(c[1]), "+f"(c[2]), "+f"(c[3])
        : "r"(a[0]), "r"(a[1]), "r"(a[2]), "r"(a[3]), "r"(b0), "r"(b1));
}
__device__ __forceinline__ void mma_f16(float* c, const uint32_t* a, uint32_t b0, uint32_t b1) {
    asm volatile(
        "mma.sync.aligned.m16n8k16.row.col.f32.f16.f16.f32 "
        "{%0,%1,%2,%3}, {%4,%5,%6,%7}, {%8,%9}, {%0,%1,%2,%3};\n"
        : "+f"(c[0]), "+f"(c[1]), "+f"(c[2]), "+f"(c[3])
        : "r"(a[0]), "r"(a[1]), "r"(a[2]), "r"(a[3]), "r"(b0), "r"(b1));
}
__device__ __forceinline__ uint32_t pack_bf16(float lo, float hi) {
    __nv_bfloat162 v = __floats2bfloat162_rn(lo, hi);
    return *(uint32_t*)&v;
}

// QKV epilogue store: n in [0,768). Block-uniform branch (64-col tiles).
__device__ __forceinline__ void store_qkv(int row, int n, float a, float b) {
    int d = n & 31;
    int hh = (n >> 5) & 7;
    if (n < 256) {
        *(uint32_t*)(g_Qb + ((size_t)hh*NN + row)*32 + d) = pack_bf16(a*QSCALE_F, b*QSCALE_F);
    } else if (n < 512) {
        *(uint32_t*)(g_Kb + ((size_t)hh*NN + row)*32 + d) = pack_bf16(a, b);
    } else {
        g_Vh[((size_t)hh*32 + d    )*NN + row] = __float2half(a);
        g_Vh[((size_t)hh*32 + d + 1)*NN + row] = __float2half(b);
    }
}

// ---------------- fused conversion kernels ----------------------------------------
__device__ __forceinline__ void tr_tile(const float* __restrict__ in, __half* __restrict__ out,
                                        int K, int N, int n0, int k0, int tid) {
    __shared__ float t[32][33];
    int tx = tid & 31, ty = tid >> 5;
    #pragma unroll
    for (int i = ty; i < 32; i += 8)
        t[i][tx] = in[(size_t)(k0 + i)*N + n0 + tx];
    __syncthreads();
    #pragma unroll
    for (int i = ty; i < 32; i += 8)
        out[(size_t)(n0 + i)*K + k0 + tx] = __float2half(t[tx][i]);
}

// prep_x: blocks [0,512) convert x -> fp16 (131072 float4s); [512,544) transpose W1.
__global__ void __launch_bounds__(256) prep_x(const float* __restrict__ x,
                                              const float* __restrict__ W1) {
    int b = blockIdx.x;
    if (b < 512) {
        int i = b * 256 + threadIdx.x;
        float4 v = ((const float4*)x)[i];
        __half2 a = __floats2half2_rn(v.x, v.y), c = __floats2half2_rn(v.z, v.w);
        ((uint2*)g_xH)[i] = make_uint2(*(uint32_t*)&a, *(uint32_t*)&c);
    } else {
        int bb = b - 512;
        tr_tile(W1, g_W1t, 128, 256, (bb & 7) * 32, (bb >> 3) * 32, threadIdx.x);
    }
}

// prep_w: blocks [0,64) W2^T; [64,128) W3^T; [128,448) cvt in_w/out_w/fp1/pd1.
__global__ void __launch_bounds__(256) prep_w(const float* __restrict__ W2,
                                              const float* __restrict__ W3,
                                              const float* __restrict__ in_w,
                                              const float* __restrict__ out_w,
                                              const float* __restrict__ fp1w,
                                              const float* __restrict__ pd1w) {
    int b = blockIdx.x;
    if (b < 64) {
        tr_tile(W2, g_W2t, 256, 256, (b & 7) * 32, (b >> 3) * 32, threadIdx.x);
    } else if (b < 128) {
        int bb = b - 64;
        tr_tile(W3, g_W3t, 256, 256, (bb & 7) * 32, (bb >> 3) * 32, threadIdx.x);
    } else {
        int i = (b - 128) * 256 + threadIdx.x;
        if (i < 196608/4) {
            float4 v = ((const float4*)in_w)[i];
            __half2 a = __floats2half2_rn(v.x, v.y), c = __floats2half2_rn(v.z, v.w);
            ((uint2*)g_inwH)[i] = make_uint2(*(uint32_t*)&a, *(uint32_t*)&c);
        }
        if (i < 65536/4) {
            float4 v = ((const float4*)out_w)[i];
            __half2 a = __floats2half2_rn(v.x, v.y), c = __floats2half2_rn(v.z, v.w);
            ((uint2*)g_outwH)[i] = make_uint2(*(uint32_t*)&a, *(uint32_t*)&c);
        }
        if (i < 32768/4) {
            float4 v = ((const float4*)fp1w)[i];
            __half2 a = __floats2half2_rn(v.x, v.y), c = __floats2half2_rn(v.z, v.w);
            ((uint2*)g_fp1H)[i] = make_uint2(*(uint32_t*)&a, *(uint32_t*)&c);
            float4 u = ((const float4*)pd1w)[i];
            __half2 d = __floats2half2_rn(u.x, u.y), e = __floats2half2_rn(u.z, u.w);
            ((uint2*)g_pd1H)[i] = make_uint2(*(uint32_t*)&d, *(uint32_t*)&e);
        }
    }
}

// ---------------- pipelined fp16 GEMM (128x64, 3-stage ring, TRANSB always) -------
template<bool RELU, bool ADDSRC, bool QKV, bool DUALB, bool OUTH>
__global__ void __launch_bounds__(256) gemm_f16(
    const __half* __restrict__ A, const __half* __restrict__ Bt,
    const __half* __restrict__ Bt2, const float* __restrict__ bias,
    const float* __restrict__ bias2, const float* __restrict__ SRC,
    void* __restrict__ Cv, void* __restrict__ C2v, int M, int N, int K)
{
    __shared__ __half As[3][128*24];
    __shared__ __half Bs[3][64*24];

    const int tid  = threadIdx.x;
    const int w    = tid >> 5, lane = tid & 31;
    const int g    = lane >> 2, t = lane & 3;
    const int wm   = w & 3, wn = w >> 2;
    const int m0   = blockIdx.y * 128;
    void* Cuse = Cv;
    int n0;
    if (DUALB) {
        n0 = (blockIdx.x & 1) * 64;
        if (blockIdx.x >= 2) { Bt = Bt2; bias = bias2; Cuse = C2v; }
    } else {
        n0 = blockIdx.x * 64;
    }
    const int KT = K >> 4;

    const int arow = tid >> 1, ac8 = (tid & 1) * 8;
    const int brow = tid >> 1, bc8 = (tid & 1) * 8;

    float acc[2][4][4] = {};

    #pragma unroll
    for (int p = 0; p < 2; p++) {
        const int k0 = p << 4;
        cp_async16(&As[p][arow*24 + ac8], A + (size_t)(m0 + arow)*K + k0 + ac8);
        if (tid < 128)
            cp_async16(&Bs[p][brow*24 + bc8], Bt + (size_t)(n0 + brow)*K + k0 + bc8);
        CP_COMMIT();
    }

    for (int kt = 0; kt < KT; kt++) {
        const int st = kt % 3;
        if (kt + 1 < KT) { CP_WAIT(1); } else { CP_WAIT(0); }
        __syncthreads();
        if (kt + 2 < KT) {
            const int sp = (kt + 2) % 3;
            const int k0 = (kt + 2) << 4;
            cp_async16(&As[sp][arow*24 + ac8], A + (size_t)(m0 + arow)*K + k0 + ac8);
            if (tid < 128)
                cp_async16(&Bs[sp][brow*24 + bc8], Bt + (size_t)(n0 + brow)*K + k0 + bc8);
            CP_COMMIT();
        }

        const uint32_t* as = (const uint32_t*)As[st];
        const uint32_t* bs = (const uint32_t*)Bs[st];
        uint32_t a[2][4];
        #pragma unroll
        for (int mt = 0; mt < 2; mt++) {
            int row = wm*32 + mt*16 + g;
            a[mt][0] = as[(row  )*12 + t];
            a[mt][1] = as[(row+8)*12 + t];
            a[mt][2] = as[(row  )*12 + t + 4];
            a[mt][3] = as[(row+8)*12 + t + 4];
        }
        #pragma unroll
        for (int nt = 0; nt < 4; nt++) {
            int n = wn*32 + nt*8 + g;
            uint32_t b0 = bs[n*12 + t];
            uint32_t b1 = bs[n*12 + t + 4];
            mma_f16(acc[0][nt], a[0], b0, b1);
            mma_f16(acc[1][nt], a[1], b0, b1);
        }
    }

    #pragma unroll
    for (int mt = 0; mt < 2; mt++) {
        const int r0 = m0 + wm*32 + mt*16 + g;
        #pragma unroll
        for (int nt = 0; nt < 4; nt++) {
            const int n = n0 + wn*32 + nt*8 + 2*t;
            float bb0 = bias ? bias[n] : 0.f;
            float bb1 = bias ? bias[n+1] : 0.f;
            float v00 = acc[mt][nt][0] + bb0, v01 = acc[mt][nt][1] + bb1;
            float v10 = acc[mt][nt][2] + bb0, v11 = acc[mt][nt][3] + bb1;
            if (ADDSRC) {
                v00 += SRC[(size_t)r0*N + n];     v01 += SRC[(size_t)r0*N + n + 1];
                v10 += SRC[(size_t)(r0+8)*N + n]; v11 += SRC[(size_t)(r0+8)*N + n + 1];
            }
            if (RELU) {
                v00 = fmaxf(v00, 0.f); v01 = fmaxf(v01, 0.f);
                v10 = fmaxf(v10, 0.f); v11 = fmaxf(v11, 0.f);
            }
            if (QKV) {
                store_qkv(r0,     n, v00, v01);
                store_qkv(r0 + 8, n, v10, v11);
            } else if (OUTH) {
                __half* C = (__half*)Cuse;
                __half2 h0 = __floats2half2_rn(v00, v01);
                __half2 h1 = __floats2half2_rn(v10, v11);
                *(uint32_t*)(C + (size_t)r0*N + n)     = *(uint32_t*)&h0;
                *(uint32_t*)(C + (size_t)(r0+8)*N + n) = *(uint32_t*)&h1;
            } else {
                float* C = (float*)Cuse;
                *(float2*)(C + (size_t)r0*N + n)     = make_float2(v00, v01);
                *(float2*)(C + (size_t)(r0+8)*N + n) = make_float2(v10, v11);
            }
        }
    }
}

// ---------------- graph preprocessing (CSR build; 4 edges/thread, int4 loads) -----
__global__ void deg_count(const int* __restrict__ dst) {
    int i = blockIdx.x * 256 + threadIdx.x;
    int4 d4 = ((const int4*)dst)[i];
    atomicAdd(&g_deg[d4.x], 1.0f);
    atomicAdd(&g_deg[d4.y], 1.0f);
    atomicAdd(&g_deg[d4.z], 1.0f);
    atomicAdd(&g_deg[d4.w], 1.0f);
}

__global__ void __launch_bounds__(1024) scan_rowptr() {
    __shared__ int warpsum[32];
    const int tid = threadIdx.x;
    const int lane = tid & 31, wid = tid >> 5;
    const int base = tid * 4;
    int c[4], s = 0;
    #pragma unroll
    for (int j = 0; j < 4; j++) {
        c[j] = (int)g_deg[base + j];
        g_dinv[base + j] = rsqrtf((float)c[j] + 1.0f);
        s += c[j];
    }
    int pre = s;
    #pragma unroll
    for (int off = 1; off < 32; off <<= 1) {
        int v = __shfl_up_sync(0xffffffffu, pre, off);
        if (lane >= off) pre += v;
    }
    if (lane == 31) warpsum[wid] = pre;
    __syncthreads();
    if (wid == 0) {
        int v = warpsum[lane];
        #pragma unroll
        for (int off = 1; off < 32; off <<= 1) {
            int u = __shfl_up_sync(0xffffffffu, v, off);
            if (lane >= off) v += u;
        }
        warpsum[lane] = v;
    }
    __syncthreads();
    int excl = pre - s + (wid > 0 ? warpsum[wid-1] : 0);
    int run = excl;
    #pragma unroll
    for (int j = 0; j < 4; j++) {
        g_rowptr[base + j] = run;
        g_cursor[base + j] = run;
        run += c[j];
    }
    if (tid == 1023) g_rowptr[NN] = run;
}

__global__ void csr_scatter(const int* __restrict__ src, const int* __restrict__ dst) {
    int i = blockIdx.x * 256 + threadIdx.x;
    int4 s4 = ((const int4*)src)[i];
    int4 d4 = ((const int4*)dst)[i];
    int sv[4] = {s4.x, s4.y, s4.z, s4.w};
    int dv[4] = {d4.x, d4.y, d4.z, d4.w};
    #pragma unroll
    for (int j = 0; j < 4; j++) {
        int p = atomicAdd(&g_cursor[dv[j]], 1);
        g_esrc[p]  = sv[j];
        g_enorm[p] = g_dinv[sv[j]] * g_dinv[dv[j]];
    }
}

// ---------------- GCN gather (fp16 in, fp16 out; H3 also writes fp32) -------------
__device__ __forceinline__ void acc_row(const uint4 v, float wgt, float* a) {
    float2 f0 = __half22float2(*(const __half2*)&v.x);
    float2 f1 = __half22float2(*(const __half2*)&v.y);
    float2 f2 = __half22float2(*(const __half2*)&v.z);
    float2 f3 = __half22float2(*(const __half2*)&v.w);
    a[0] = fmaf(wgt, f0.x, a[0]); a[1] = fmaf(wgt, f0.y, a[1]);
    a[2] = fmaf(wgt, f1.x, a[2]); a[3] = fmaf(wgt, f1.y, a[3]);
    a[4] = fmaf(wgt, f2.x, a[4]); a[5] = fmaf(wgt, f2.y, a[5]);
    a[6] = fmaf(wgt, f3.x, a[6]); a[7] = fmaf(wgt, f3.y, a[7]);
}

template<bool RELU, bool H3>
__global__ void __launch_bounds__(256) gcn_gather(const float* __restrict__ bias,
                                                  __half* __restrict__ outH,
                                                  float* __restrict__ outF) {
    const int node = blockIdx.x * 8 + (threadIdx.x >> 5);
    const int lane = threadIdx.x & 31;
    const int beg = g_rowptr[node], end = g_rowptr[node+1];

    float a[8] = {};
    int i = beg;
    for (; i + 2 <= end; i += 2) {
        int s0i = g_esrc[i],   s1i = g_esrc[i+1];
        float w0 = g_enorm[i], w1 = g_enorm[i+1];
        uint4 x = *((const uint4*)(g_tmpH + (size_t)s0i*HH) + lane);
        uint4 y = *((const uint4*)(g_tmpH + (size_t)s1i*HH) + lane);
        acc_row(x, w0, a);
        acc_row(y, w1, a);
    }
    if (i < end) {
        uint4 x = *((const uint4*)(g_tmpH + (size_t)g_esrc[i]*HH) + lane);
        acc_row(x, g_enorm[i], a);
    }
    float di = g_dinv[node];
    float sw = di * di;
    uint4 sv = *((const uint4*)(g_tmpH + (size_t)node*HH) + lane);
    acc_row(sv, sw, a);

    const float4* bp = (const float4*)(bias + lane*8);
    float4 b0 = bp[0], b1 = bp[1];
    float o0 = a[0] + b0.x, o1 = a[1] + b0.y, o2 = a[2] + b0.z, o3 = a[3] + b0.w;
    float o4 = a[4] + b1.x, o5 = a[5] + b1.y, o6 = a[6] + b1.z, o7 = a[7] + b1.w;
    if (RELU) {
        o0 = fmaxf(o0,0.f); o1 = fmaxf(o1,0.f); o2 = fmaxf(o2,0.f); o3 = fmaxf(o3,0.f);
        o4 = fmaxf(o4,0.f); o5 = fmaxf(o5,0.f); o6 = fmaxf(o6,0.f); o7 = fmaxf(o7,0.f);
    }
    __half2 ph0 = __floats2half2_rn(o0,o1), ph1 = __floats2half2_rn(o2,o3);
    __half2 ph2 = __floats2half2_rn(o4,o5), ph3 = __floats2half2_rn(o6,o7);
    *((uint4*)(outH + (size_t)node*HH) + lane) =
        make_uint4(*(uint32_t*)&ph0, *(uint32_t*)&ph1, *(uint32_t*)&ph2, *(uint32_t*)&ph3);
    if (H3) {
        float4* op = (float4*)(outF + (size_t)node*HH + lane*8);
        op[0] = make_float4(o0,o1,o2,o3);
        op[1] = make_float4(o4,o5,o6,o7);
    }
}

// ---------------- split-KV flash attention (2 CTAs/SM) -----------------------------
// grid (NN/256, 8, 2): z = key split (2048 keys each). Unnormalized partials out.
__global__ void __launch_bounds__(256, 2) flash_attn_bf16() {
    __shared__ __align__(16) char Ks[3][64*80];
    __shared__ __align__(16) char Vs[3][32*144];

    const int head  = blockIdx.y;
    const int split = blockIdx.z;
    const int q0    = blockIdx.x * 256;
    const int kb0   = split * 2048;
    const int tid   = threadIdx.x;
    const int w     = tid >> 5, lane = tid & 31;
    const int g     = lane >> 2, t = lane & 3;
    const int KT    = 2048 / 64;
    const uint32_t ONES2 = 0x3C003C00u;

    const __nv_bfloat16* kg = g_Kb + (size_t)head*NN*32 + (size_t)kb0*32;
    const __half*        vg = g_Vh + (size_t)head*32*NN + kb0;

    const int kr8 = tid >> 2, kc8 = (tid & 3) * 8;
    const int vd  = tid >> 3, vk8 = (tid & 7) * 8;

    cp_async16(&Ks[0][kr8*80 + kc8*2], kg + (size_t)kr8*32 + kc8);
    cp_async16(&Vs[0][vd*144 + vk8*2], vg + (size_t)vd*NN + vk8);
    CP_COMMIT();
    cp_async16(&Ks[1][kr8*80 + kc8*2], kg + (size_t)(64 + kr8)*32 + kc8);
    cp_async16(&Vs[1][vd*144 + vk8*2], vg + (size_t)vd*NN + 64 + vk8);
    CP_COMMIT();

    uint32_t aq[2][2][4];
    #pragma unroll
    for (int qh = 0; qh < 2; qh++) {
        const __nv_bfloat16* qb = g_Qb + ((size_t)head*NN + q0 + qh*128 + w*16) * 32;
        #pragma unroll
        for (int ks = 0; ks < 2; ks++) {
            int c = ks*16 + 2*t;
            aq[qh][ks][0] = *(const uint32_t*)(qb + (size_t)(g  )*32 + c);
            aq[qh][ks][1] = *(const uint32_t*)(qb + (size_t)(g+8)*32 + c);
            aq[qh][ks][2] = *(const uint32_t*)(qb + (size_t)(g  )*32 + c + 8);
            aq[qh][ks][3] = *(const uint32_t*)(qb + (size_t)(g+8)*32 + c + 8);
        }
    }

    float m[2][2];
    m[0][0] = m[0][1] = m[1][0] = m[1][1] = -1e30f;
    float o[2][4][4] = {};
    float lacc[2][4] = {};

    for (int kt = 0; kt < KT; kt++) {
        const int st = kt % 3;
        if (kt + 1 < KT) { CP_WAIT(1); } else { CP_WAIT(0); }
        __syncthreads();
        if (kt + 2 < KT) {
            const int sp = (kt + 2) % 3;
            cp_async16(&Ks[sp][kr8*80 + kc8*2], kg + (size_t)((kt+2)*64 + kr8)*32 + kc8);
            cp_async16(&Vs[sp][vd*144 + vk8*2], vg + (size_t)vd*NN + (kt+2)*64 + vk8);
            CP_COMMIT();
        }

        #pragma unroll
        for (int qh = 0; qh < 2; qh++) {
            float s[8][4];
            #pragma unroll
            for (int nb = 0; nb < 8; nb++) {
                s[nb][0] = s[nb][1] = s[nb][2] = s[nb][3] = 0.f;
                const char* kr = Ks[st] + (nb*8 + g)*80;
                uint32_t b0 = *(const uint32_t*)(kr + (2*t)*2);
                uint32_t b1 = *(const uint32_t*)(kr + (2*t+8)*2);
                mma_bf16(s[nb], aq[qh][0], b0, b1);
                b0 = *(const uint32_t*)(kr + (16 + 2*t)*2);
                b1 = *(const uint32_t*)(kr + (16 + 2*t+8)*2);
                mma_bf16(s[nb], aq[qh][1], b0, b1);
            }

            float tm0 = -1e30f, tm1 = -1e30f;
            #pragma unroll
            for (int nb = 0; nb < 8; nb++) {
                tm0 = fmaxf(tm0, fmaxf(s[nb][0], s[nb][1]));
                tm1 = fmaxf(tm1, fmaxf(s[nb][2], s[nb][3]));
            }
            tm0 = fmaxf(tm0, __shfl_xor_sync(0xffffffffu, tm0, 1));
            tm0 = fmaxf(tm0, __shfl_xor_sync(0xffffffffu, tm0, 2));
            tm1 = fmaxf(tm1, __shfl_xor_sync(0xffffffffu, tm1, 1));
            tm1 = fmaxf(tm1, __shfl_xor_sync(0xffffffffu, tm1, 2));
            float nm0 = fmaxf(m[qh][0], tm0), nm1 = fmaxf(m[qh][1], tm1);
            float al0 = exp2f(m[qh][0] - nm0), al1 = exp2f(m[qh][1] - nm1);
            m[qh][0] = nm0; m[qh][1] = nm1;

            __half2 p01[8], p23[8];
            #pragma unroll
            for (int nb = 0; nb < 8; nb++) {
                p01[nb] = h2exp2(__floats2half2_rn(s[nb][0] - nm0, s[nb][1] - nm0));
                p23[nb] = h2exp2(__floats2half2_rn(s[nb][2] - nm1, s[nb][3] - nm1));
            }

            #pragma unroll
            for (int nbv = 0; nbv < 4; nbv++) {
                o[qh][nbv][0] *= al0; o[qh][nbv][1] *= al0;
                o[qh][nbv][2] *= al1; o[qh][nbv][3] *= al1;
            }
            lacc[qh][0] *= al0; lacc[qh][1] *= al0;
            lacc[qh][2] *= al1; lacc[qh][3] *= al1;

            uint32_t ap[4][4];
            #pragma unroll
            for (int s4 = 0; s4 < 4; s4++) {
                ap[s4][0] = *(const uint32_t*)&p01[2*s4];
                ap[s4][1] = *(const uint32_t*)&p23[2*s4];
                ap[s4][2] = *(const uint32_t*)&p01[2*s4+1];
                ap[s4][3] = *(const uint32_t*)&p23[2*s4+1];
            }

            #pragma unroll
            for (int s4 = 0; s4 < 4; s4++) {
                mma_f16(lacc[qh], ap[s4], ONES2, ONES2);
                #pragma unroll
                for (int nbv = 0; nbv < 4; nbv++) {
                    const char* vr = Vs[st] + (nbv*8 + g)*144;
                    uint32_t b0 = *(const uint32_t*)(vr + (16*s4 + 2*t)*2);
                    uint32_t b1 = *(const uint32_t*)(vr + (16*s4 + 2*t + 8)*2);
                    mma_f16(o[qh][nbv], ap[s4], b0, b1);
                }
            }
        }
    }

    // epilogue: unnormalized partial O + (m, l) per row
    float* po = g_po[split];
    #pragma unroll
    for (int qh = 0; qh < 2; qh++) {
        int row0 = q0 + qh*128 + w*16 + g;
        #pragma unroll
        for (int nbv = 0; nbv < 4; nbv++) {
            int col = head*32 + nbv*8 + 2*t;
            *(float2*)(po + (size_t)row0*HH + col)     = make_float2(o[qh][nbv][0], o[qh][nbv][1]);
            *(float2*)(po + (size_t)(row0+8)*HH + col) = make_float2(o[qh][nbv][2], o[qh][nbv][3]);
        }
        if (t == 0) {
            size_t base = ((size_t)split*8 + head)*NN;
            g_pm[base + row0]     = m[qh][0];
            g_pl[base + row0]     = lacc[qh][0];
            g_pm[base + row0 + 8] = m[qh][1];
            g_pl[base + row0 + 8] = lacc[qh][2];
        }
    }
}

// merge the two KV splits: warp per node, lane covers 8 cols (single head per lane).
__global__ void __launch_bounds__(256) attn_merge() {
    const int node = blockIdx.x * 8 + (threadIdx.x >> 5);
    const int lane = threadIdx.x & 31;
    const int head = lane >> 2;

    float m0 = g_pm[(size_t)head*NN + node];
    float l0 = g_pl[(size_t)head*NN + node];
    float m1 = g_pm[(size_t)(8 + head)*NN + node];
    float l1 = g_pl[(size_t)(8 + head)*NN + node];
    float M  = fmaxf(m0, m1);
    float w0 = exp2f(m0 - M), w1 = exp2f(m1 - M);
    float inv = 1.0f / (l0*w0 + l1*w1);
    w0 *= inv; w1 *= inv;

    const float4* p0 = (const float4*)(g_po[0] + (size_t)node*HH + lane*8);
    const float4* p1 = (const float4*)(g_po[1] + (size_t)node*HH + lane*8);
    float4 a0 = p0[0], a1 = p0[1], c0 = p1[0], c1 = p1[1];
    __half2 h0 = __floats2half2_rn(a0.x*w0 + c0.x*w1, a0.y*w0 + c0.y*w1);
    __half2 h1 = __floats2half2_rn(a0.z*w0 + c0.z*w1, a0.w*w0 + c0.w*w1);
    __half2 h2 = __floats2half2_rn(a1.x*w0 + c1.x*w1, a1.y*w0 + c1.y*w1);
    __half2 h3 = __floats2half2_rn(a1.z*w0 + c1.z*w1, a1.w*w0 + c1.w*w1);
    *((uint4*)(g_attnH + (size_t)node*HH) + lane) =
        make_uint4(*(uint32_t*)&h0, *(uint32_t*)&h1, *(uint32_t*)&h2, *(uint32_t*)&h3);
}

// ---------------- fused output heads (warp per node: softmax3 + sigmoid10) --------
__global__ void __launch_bounds__(256) head_both(const float* __restrict__ W3,
                                                 const float* __restrict__ b3v,
                                                 const float* __restrict__ W10,
                                                 const float* __restrict__ b10,
                                                 float* __restrict__ out) {
    const int node = blockIdx.x * 8 + (threadIdx.x >> 5);
    const int lane = threadIdx.x & 31;

    float4 hv = *(const float4*)(g_hid + (size_t)node*128 + lane*4);
    float lg3[3];
    #pragma unroll
    for (int c = 0; c < 3; c++) {
        float4 wv = *(const float4*)(W3 + c*128 + lane*4);
        float d = hv.x*wv.x + hv.y*wv.y + hv.z*wv.z + hv.w*wv.w;
        #pragma unroll
        for (int m = 16; m >= 1; m >>= 1) d += __shfl_xor_sync(0xffffffffu, d, m);
        lg3[c] = d + b3v[c];
    }
    float4 hv2 = *(const float4*)(g_hid2 + (size_t)node*128 + lane*4);
    float lg10[10];
    #pragma unroll
    for (int c = 0; c < 10; c++) {
        float4 wv = *(const float4*)(W10 + c*128 + lane*4);
        float d = hv2.x*wv.x + hv2.y*wv.y + hv2.z*wv.z + hv2.w*wv.w;
        #pragma unroll
        for (int m = 16; m >= 1; m >>= 1) d += __shfl_xor_sync(0xffffffffu, d, m);
        lg10[c] = d + b10[c];
    }
    if (lane == 0) {
        float mx = fmaxf(fmaxf(lg3[0], lg3[1]), lg3[2]);
        float e0 = __expf(lg3[0]-mx), e1 = __expf(lg3[1]-mx), e2 = __expf(lg3[2]-mx);
        float inv = 1.0f / (e0 + e1 + e2);
        out[(size_t)node*3 + 0] = e0*inv;
        out[(size_t)node*3 + 1] = e1*inv;
        out[(size_t)node*3 + 2] = e2*inv;
        float* o2 = out + (size_t)NN*3 + (size_t)node*10;
        #pragma unroll
        for (int c = 0; c < 10; c++)
            o2[c] = 1.0f / (1.0f + __expf(-lg10[c]));
    }
}

// ---------------- launch ---------------------------------------------------------
extern "C" void kernel_launch(void* const* d_in, const int* in_sizes, int n_in,
                              void* d_out, int out_size)
{
    const float* x     = (const float*)d_in[0];
    const int*   ei    = (const int*)  d_in[1];
    const float* W1    = (const float*)d_in[2];
    const float* b1    = (const float*)d_in[3];
    const float* W2    = (const float*)d_in[4];
    const float* b2    = (const float*)d_in[5];
    const float* W3    = (const float*)d_in[6];
    const float* b3    = (const float*)d_in[7];
    const float* in_w  = (const float*)d_in[8];
    const float* in_b  = (const float*)d_in[9];
    const float* out_w = (const float*)d_in[10];
    const float* out_b = (const float*)d_in[11];
    const float* fp1w  = (const float*)d_in[12];
    const float* fp1b  = (const float*)d_in[13];
    const float* fp2w  = (const float*)d_in[14];
    const float* fp2b  = (const float*)d_in[15];
    const float* pd1w  = (const float*)d_in[16];
    const float* pd1b  = (const float*)d_in[17];
    const float* pd2w  = (const float*)d_in[18];
    const float* pd2b  = (const float*)d_in[19];
    const int* src = ei;
    const int* dst = ei + EE;
    float* outp = (float*)d_out;

    void *tmph, *hh, *h3h, *attnh, *xh, *w1t, *w2t, *w3t, *inwh, *outwh, *fp1h, *pd1h;
    float *h3, *deg, *hid, *hid2;
    cudaGetSymbolAddress((void**)&tmph,  g_tmpH);
    cudaGetSymbolAddress((void**)&hh,    g_hH);
    cudaGetSymbolAddress((void**)&h3h,   g_h3H);
    cudaGetSymbolAddress((void**)&h3,    g_h3);
    cudaGetSymbolAddress((void**)&attnh, g_attnH);
    cudaGetSymbolAddress((void**)&deg,   g_deg);
    cudaGetSymbolAddress((void**)&hid,   g_hid);
    cudaGetSymbolAddress((void**)&hid2,  g_hid2);
    cudaGetSymbolAddress((void**)&xh,    g_xH);
    cudaGetSymbolAddress((void**)&w1t,   g_W1t);
    cudaGetSymbolAddress((void**)&w2t,   g_W2t);
    cudaGetSymbolAddress((void**)&w3t,   g_W3t);
    cudaGetSymbolAddress((void**)&inwh,  g_inwH);
    cudaGetSymbolAddress((void**)&outwh, g_outwH);
    cudaGetSymbolAddress((void**)&fp1h,  g_fp1H);
    cudaGetSymbolAddress((void**)&pd1h,  g_pd1H);

    static cudaStream_t s2 = nullptr;
    static cudaEvent_t evF = nullptr, evJ = nullptr, evW = nullptr;
    if (!s2) {
        cudaStreamCreateWithFlags(&s2, cudaStreamNonBlocking);
        cudaEventCreateWithFlags(&evF, cudaEventDisableTiming);
        cudaEventCreateWithFlags(&evJ, cudaEventDisableTiming);
        cudaEventCreateWithFlags(&evW, cudaEventDisableTiming);
    }

    const dim3 blk(256);

    // Fork: CSR build FIRST on s2 (join feeds gather1), then fused weight prep.
    cudaEventRecord(evF, 0);
    cudaStreamWaitEvent(s2, evF, 0);
    cudaMemsetAsync(deg, 0, NN * sizeof(float), s2);
    deg_count<<<EE/1024, 256, 0, s2>>>(dst);
    scan_rowptr<<<1, 1024, 0, s2>>>();
    csr_scatter<<<EE/1024, 256, 0, s2>>>(src, dst);
    cudaEventRecord(evJ, s2);
    prep_w<<<448, blk, 0, s2>>>(W2, W3, in_w, out_w, fp1w, pd1w);
    cudaEventRecord(evW, s2);

    prep_x<<<544, blk>>>(x, W1);
    gemm_f16<false,false,false,false,true><<<dim3(4,32), blk>>>(
        (const __half*)xh, (const __half*)w1t, nullptr, nullptr, nullptr, nullptr,
        tmph, nullptr, NN, HH, 128);
    cudaStreamWaitEvent(0, evJ, 0);     // CSR ready

    gcn_gather<true,false><<<NN/8, blk>>>(b1, (__half*)hh, nullptr);
    cudaStreamWaitEvent(0, evW, 0);     // weight prep ready (overlapped w/ gather1)
    gemm_f16<false,false,false,false,true><<<dim3(4,32), blk>>>(
        (const __half*)hh, (const __half*)w2t, nullptr, nullptr, nullptr, nullptr,
        tmph, nullptr, NN, HH, HH);
    gcn_gather<true,false><<<NN/8, blk>>>(b2, (__half*)hh, nullptr);
    gemm_f16<false,false,false,false,true><<<dim3(4,32), blk>>>(
        (const __half*)hh, (const __half*)w3t, nullptr, nullptr, nullptr, nullptr,
        tmph, nullptr, NN, HH, HH);
    gcn_gather<false,true><<<NN/8, blk>>>(b3, (__half*)h3h, h3);

    // MHA: fused QKV gemm; split-KV flash attention (2 CTAs/SM) + merge
    gemm_f16<false,false,true,false,false><<<dim3(12,32), blk>>>(
        (const __half*)h3h, (const __half*)inwh, nullptr, in_b, nullptr, nullptr,
        nullptr, nullptr, NN, 3*HH, HH);
    flash_attn_bf16<<<dim3(NN/256, 8, 2), blk>>>();
    attn_merge<<<NN/8, blk>>>();
    gemm_f16<false,true,false,false,true><<<dim3(4,32), blk>>>(
        (const __half*)attnh, (const __half*)outwh, nullptr, out_b, nullptr, h3,
        hh, nullptr, NN, HH, HH);

    // Fused dual-head GEMM + fused heads
    gemm_f16<true,false,false,true,false><<<dim3(4,32), blk>>>(
        (const __half*)hh, (const __half*)fp1h, (const __half*)pd1h, fp1b, pd1b, nullptr,
        hid, hid2, NN, 128, HH);
    head_both<<<NN/8, blk>>>(fp2w, fp2b, pd2w, pd2b, outp);
}